// round 1
// baseline (speedup 1.0000x reference)
#include <cuda_runtime.h>
#include <math.h>

#define BSZ 32
#define LL 4096
#define HH 512
#define PP 384
#define VV 32
#define TOUT 16
#define NC 16
#define CHUNK 255          // (LL - TOUT) / NC
#define RR (BSZ*TOUT)      // 512 output rows
#define SPLITK 4

// ---------------- scratch (device globals; no allocation allowed) ----------------
__device__ float2  d_Lbar[PP];
__device__ float2  d_g[PP];
__device__ double2 d_W[PP];                 // Lbar^CHUNK in double (exact power of fp32 Lbar)
__device__ float2  d_Bg[VV*PP];             // g_p * (embed_v . Bc_p)
__device__ float2  d_xpart[BSZ*NC*PP];
__device__ float   d_Xbig[RR*2*PP];         // [r][768] = [2*x_re | -2*x_im]
__device__ float   d_Cbig[2*PP*HH];         // [768][512] = [C_re^T ; C_im^T]
__device__ float   d_ud[RR*HH];             // u*D term
__device__ float   d_y[RR*HH];
__device__ float   d_h1[RR*HH];
__device__ float   d_part[SPLITK*RR*HH];    // split-K partials (reused by both GEMMs)

// ---------------- K1a: per-mode constants ----------------
__global__ void prep_lbar(const float* __restrict__ Lre, const float* __restrict__ Lim,
                          const float* __restrict__ logstep) {
    int p = threadIdx.x;
    if (p >= PP) return;
    float lre = Lre[p], lim = Lim[p];
    float step = (float)exp((double)logstep[p]);
    float zr = lre * step, zi = lim * step;
    double m = exp((double)zr);
    double sv, cv; sincos((double)zi, &sv, &cv);
    float br = (float)(m * cv), bi = (float)(m * sv);
    d_Lbar[p] = make_float2(br, bi);
    // g = (Lbar - 1) / Lam   (complex, fp32 like reference)
    float ar = br - 1.f, ai = bi;
    float den = lre*lre + lim*lim;
    d_g[p] = make_float2((ar*lre + ai*lim)/den, (ai*lre - ar*lim)/den);
    // W = (fp32 Lbar)^CHUNK computed exactly in double
    double dbr = (double)br, dbi = (double)bi;
    double r  = sqrt(dbr*dbr + dbi*dbi);
    double mm = exp(log(r) * (double)CHUNK);
    double th = atan2(dbi, dbr) * (double)CHUNK;
    double s2, c2; sincos(th, &s2, &c2);
    d_W[p] = make_double2(mm*c2, mm*s2);
}

// ---------------- K1b: Bg[v][p] = g_p * sum_h embed[v,h]*Bc[p,h] ----------------
__global__ void prep_bg(const float* __restrict__ embed, const float* __restrict__ Bre,
                        const float* __restrict__ Bim) {
    __shared__ float sBr[HH], sBi[HH];
    int p = blockIdx.x;
    for (int h = threadIdx.x; h < HH; h += blockDim.x) {
        sBr[h] = Bre[p*HH + h];
        sBi[h] = Bim[p*HH + h];
    }
    __syncthreads();
    int warp = threadIdx.x >> 5, lane = threadIdx.x & 31;
    float2 g = d_g[p];
    for (int v = warp; v < VV; v += 8) {
        float sr = 0.f, si = 0.f;
        for (int h = lane; h < HH; h += 32) {
            float e = embed[v*HH + h];
            sr = fmaf(e, sBr[h], sr);
            si = fmaf(e, sBi[h], si);
        }
        #pragma unroll
        for (int o = 16; o; o >>= 1) {
            sr += __shfl_xor_sync(0xffffffffu, sr, o);
            si += __shfl_xor_sync(0xffffffffu, si, o);
        }
        if (lane == 0)
            d_Bg[v*PP + p] = make_float2(g.x*sr - g.y*si, g.x*si + g.y*sr);
    }
}

// ---------------- K2: chunked scan (per-chunk geometric reduction) ----------------
__global__ void __launch_bounds__(PP) scan_chunks(const int* __restrict__ tokens) {
    extern __shared__ float smf[];
    float2* sBg = (float2*)smf;                  // VV*PP float2 = 98304 B
    int* stok = (int*)(smf + 2*VV*PP);           // CHUNK ints
    int b = blockIdx.y, c = blockIdx.x, p = threadIdx.x;
    for (int i = p; i < VV*PP; i += PP) sBg[i] = d_Bg[i];
    const int s0 = c * CHUNK;
    for (int i = p; i < CHUNK; i += PP) stok[i] = tokens[b*LL + s0 + i];
    __syncthreads();
    float2 Lb = d_Lbar[p];
    float xr = 0.f, xi = 0.f;
    #pragma unroll 5
    for (int i = 0; i < CHUNK; ++i) {
        float2 bg = sBg[stok[i]*PP + p];
        float nr = fmaf(Lb.x, xr, fmaf(-Lb.y, xi, bg.x));
        float ni = fmaf(Lb.y, xr, fmaf( Lb.x, xi, bg.y));
        xr = nr; xi = ni;
    }
    d_xpart[(b*NC + c)*PP + p] = make_float2(xr, xi);
}

// ---------------- K3: combine chunks + 16 emission steps ----------------
__global__ void combine_emit(const int* __restrict__ tokens) {
    int b = blockIdx.x, p = threadIdx.x;
    float2 Lb = d_Lbar[p];
    double2 W = d_W[p];
    double pwr = 1.0, pwi = 0.0, axr = 0.0, axi = 0.0;
    for (int c = NC - 1; c >= 0; --c) {
        float2 xp = d_xpart[(b*NC + c)*PP + p];
        axr += pwr*xp.x - pwi*xp.y;
        axi += pwr*xp.y + pwi*xp.x;
        double nr = pwr*W.x - pwi*W.y;
        double ni = pwr*W.y + pwi*W.x;
        pwr = nr; pwi = ni;
    }
    float xr = (float)axr, xi = (float)axi;
    for (int j = 0; j < TOUT; ++j) {
        int tok = tokens[b*LL + (LL - TOUT) + j];
        float2 bg = d_Bg[tok*PP + p];
        float nr = fmaf(Lb.x, xr, fmaf(-Lb.y, xi, bg.x));
        float ni = fmaf(Lb.y, xr, fmaf( Lb.x, xi, bg.y));
        xr = nr; xi = ni;
        int r = b*TOUT + j;
        d_Xbig[r*(2*PP) + p]      =  2.f * xr;
        d_Xbig[r*(2*PP) + PP + p] = -2.f * xi;
    }
}

// ---------------- small prep kernels ----------------
__global__ void prep_cbig(const float* __restrict__ Cre, const float* __restrict__ Cim) {
    int idx = blockIdx.x*256 + threadIdx.x;      // 2*PP*HH total
    int k = idx / HH, h = idx % HH;
    d_Cbig[idx] = (k < PP) ? Cre[h*PP + k] : Cim[h*PP + (k - PP)];
}

__global__ void prep_ud(const int* __restrict__ tokens, const float* __restrict__ embed,
                        const float* __restrict__ D) {
    int idx = blockIdx.x*256 + threadIdx.x;      // RR*HH total
    int r = idx / HH, h = idx % HH;
    int b = r / TOUT, j = r % TOUT;
    int tok = tokens[b*LL + (LL - TOUT) + j];
    d_ud[idx] = embed[tok*HH + h] * D[h];
}

// ---------------- split-K fp32 GEMM (M=N=512) ----------------
__device__ __forceinline__ void gemm_body(const float* __restrict__ A,
                                          const float* __restrict__ B,
                                          float* __restrict__ Cp, int K) {
    __shared__ float sA[16][65];
    __shared__ float sB[16][64];
    int tid = threadIdx.x;
    int tn = tid & 15, tm = tid >> 4;
    int row0 = blockIdx.y * 64, col0 = blockIdx.x * 64;
    int kchunk = K / SPLITK;
    int k0 = blockIdx.z * kchunk;
    float acc[4][4] = {};
    int arow = tid >> 2;
    int acol = (tid & 3) * 4;
    int brow = tid >> 4;
    int bcol = (tid & 15) * 4;
    for (int kk = 0; kk < kchunk; kk += 16) {
        float4 av = *(const float4*)(A + (size_t)(row0 + arow)*K + k0 + kk + acol);
        float4 bv = *(const float4*)(B + (size_t)(k0 + kk + brow)*HH + col0 + bcol);
        sA[acol+0][arow] = av.x; sA[acol+1][arow] = av.y;
        sA[acol+2][arow] = av.z; sA[acol+3][arow] = av.w;
        *(float4*)&sB[brow][bcol] = bv;
        __syncthreads();
        #pragma unroll
        for (int k = 0; k < 16; ++k) {
            float a0 = sA[k][tm*4+0], a1 = sA[k][tm*4+1];
            float a2 = sA[k][tm*4+2], a3 = sA[k][tm*4+3];
            float4 bb = *(const float4*)&sB[k][tn*4];
            acc[0][0]=fmaf(a0,bb.x,acc[0][0]); acc[0][1]=fmaf(a0,bb.y,acc[0][1]);
            acc[0][2]=fmaf(a0,bb.z,acc[0][2]); acc[0][3]=fmaf(a0,bb.w,acc[0][3]);
            acc[1][0]=fmaf(a1,bb.x,acc[1][0]); acc[1][1]=fmaf(a1,bb.y,acc[1][1]);
            acc[1][2]=fmaf(a1,bb.z,acc[1][2]); acc[1][3]=fmaf(a1,bb.w,acc[1][3]);
            acc[2][0]=fmaf(a2,bb.x,acc[2][0]); acc[2][1]=fmaf(a2,bb.y,acc[2][1]);
            acc[2][2]=fmaf(a2,bb.z,acc[2][2]); acc[2][3]=fmaf(a2,bb.w,acc[2][3]);
            acc[3][0]=fmaf(a3,bb.x,acc[3][0]); acc[3][1]=fmaf(a3,bb.y,acc[3][1]);
            acc[3][2]=fmaf(a3,bb.z,acc[3][2]); acc[3][3]=fmaf(a3,bb.w,acc[3][3]);
        }
        __syncthreads();
    }
    float* Cb = Cp + (size_t)blockIdx.z * (RR*HH);
    #pragma unroll
    for (int i = 0; i < 4; ++i)
        #pragma unroll
        for (int j = 0; j < 4; ++j)
            Cb[(size_t)(row0 + tm*4 + i)*HH + col0 + tn*4 + j] = acc[i][j];
}

__global__ void __launch_bounds__(256) gemm_xc() {
    gemm_body(d_Xbig, d_Cbig, d_part, 2*PP);
}
__global__ void __launch_bounds__(256) gemm_yw(const float* __restrict__ W1) {
    gemm_body(d_y, W1, d_part, HH);
}

__global__ void reduce_y() {
    int i = blockIdx.x*256 + threadIdx.x;
    float s = d_ud[i];
    #pragma unroll
    for (int z = 0; z < SPLITK; ++z) s += d_part[(size_t)z*RR*HH + i];
    d_y[i] = s;
}
__global__ void reduce_h1(const float* __restrict__ b1) {
    int i = blockIdx.x*256 + threadIdx.x;
    float s = b1[i % HH];
    #pragma unroll
    for (int z = 0; z < SPLITK; ++z) s += d_part[(size_t)z*RR*HH + i];
    d_h1[i] = fmaxf(s, 0.f);
}

// ---------------- final tiny GEMM: out = h1 @ W2 + b2 ----------------
__global__ void final_out(const float* __restrict__ W2, const float* __restrict__ b2,
                          float* __restrict__ out) {
    int idx = blockIdx.x*256 + threadIdx.x;      // RR*VV = 16384
    int r = idx >> 5, v = idx & 31;
    float acc = b2[v];
    const float* hrow = d_h1 + (size_t)r*HH;
    #pragma unroll 8
    for (int h = 0; h < HH; ++h)
        acc = fmaf(hrow[h], W2[h*VV + v], acc);
    out[idx] = acc;
}

// ---------------- launcher ----------------
extern "C" void kernel_launch(void* const* d_in, const int* in_sizes, int n_in,
                              void* d_out, int out_size) {
    const int*   tokens  = (const int*)  d_in[0];
    const float* embed   = (const float*)d_in[1];
    const float* Lre     = (const float*)d_in[2];
    const float* Lim     = (const float*)d_in[3];
    const float* Bre     = (const float*)d_in[4];
    const float* Bim     = (const float*)d_in[5];
    const float* Cre     = (const float*)d_in[6];
    const float* Cim     = (const float*)d_in[7];
    const float* D       = (const float*)d_in[8];
    const float* logstep = (const float*)d_in[9];
    const float* W1      = (const float*)d_in[10];
    const float* b1      = (const float*)d_in[11];
    const float* W2      = (const float*)d_in[12];
    const float* b2      = (const float*)d_in[13];
    float* out = (float*)d_out;

    const size_t scan_smem = (size_t)VV*PP*sizeof(float2) + (size_t)CHUNK*sizeof(int);
    cudaFuncSetAttribute(scan_chunks, cudaFuncAttributeMaxDynamicSharedMemorySize,
                         (int)scan_smem);

    prep_lbar<<<1, PP>>>(Lre, Lim, logstep);
    prep_bg<<<PP, 256>>>(embed, Bre, Bim);
    scan_chunks<<<dim3(NC, BSZ), PP, scan_smem>>>(tokens);
    combine_emit<<<BSZ, PP>>>(tokens);
    prep_cbig<<<(2*PP*HH)/256, 256>>>(Cre, Cim);
    prep_ud<<<(RR*HH)/256, 256>>>(tokens, embed, D);

    gemm_xc<<<dim3(8, 8, SPLITK), 256>>>();
    reduce_y<<<(RR*HH)/256, 256>>>();
    gemm_yw<<<dim3(8, 8, SPLITK), 256>>>(W1);
    reduce_h1<<<(RR*HH)/256, 256>>>(b1);
    final_out<<<(RR*VV)/256, 256>>>(W2, b2, out);
}

// round 2
// speedup vs baseline: 1.0640x; 1.0640x over previous
#include <cuda_runtime.h>
#include <math.h>

#define BSZ 32
#define LL 4096
#define HH 512
#define PP 384
#define VV 32
#define TOUT 16
#define NC 16
#define CHUNK 255          // (LL - TOUT) / NC
#define RR (BSZ*TOUT)      // 512 output rows
#define SPLITK 4

typedef unsigned long long u64;

// ---------------- scratch (device globals; no allocation allowed) ----------------
__device__ __align__(16) float2 d_Lbar[PP];
__device__ float2               d_g[PP];
__device__ __align__(16) float2 d_Wpow[NC*PP];     // W^k per mode, k=0..NC-1 (W=Lbar^CHUNK)
__device__ __align__(16) float2 d_Bg[VV*PP];       // g_p * (embed_v . Bc_p)
__device__ __align__(16) float2 d_xpart[BSZ*NC*PP];
__device__ __align__(16) float  d_Xbig[RR*2*PP];   // [r][768] = [2*x_re | -2*x_im]
__device__ __align__(16) float  d_Cbig[2*PP*HH];   // [768][512] = [C_re^T ; C_im^T]
__device__ __align__(16) float  d_y[RR*HH];
__device__ __align__(16) float  d_h1[RR*HH];
__device__ __align__(16) float  d_part[SPLITK*RR*HH];

// ---------------- packed f32x2 helpers ----------------
__device__ __forceinline__ u64 pk2(float lo, float hi) {
    u64 r; asm("mov.b64 %0, {%1, %2};" : "=l"(r) : "f"(lo), "f"(hi)); return r;
}
__device__ __forceinline__ float2 upk(u64 x) {
    float lo, hi; asm("mov.b64 {%0, %1}, %2;" : "=f"(lo), "=f"(hi) : "l"(x));
    return make_float2(lo, hi);
}
__device__ __forceinline__ u64 swp(u64 x) {
    u64 r;
    asm("{\n\t.reg .b32 a, b;\n\tmov.b64 {a, b}, %1;\n\tmov.b64 %0, {b, a};\n\t}"
        : "=l"(r) : "l"(x));
    return r;
}
__device__ __forceinline__ u64 fma2(u64 a, u64 b, u64 c) {
    u64 d; asm("fma.rn.f32x2 %0, %1, %2, %3;" : "=l"(d) : "l"(a), "l"(b), "l"(c));
    return d;
}
// one complex step: X = Lbar*X + BG, packed as (re, im)
__device__ __forceinline__ void cstep(u64& X, u64 Lp, u64 Lm, u64 BG) {
    X = fma2(Lp, X, fma2(Lm, swp(X), BG));
}

// ---------------- K1a: per-mode constants + chunk-power table ----------------
__global__ void prep_lbar(const float* __restrict__ Lre, const float* __restrict__ Lim,
                          const float* __restrict__ logstep) {
    int p = threadIdx.x;
    if (p >= PP) return;
    float lre = Lre[p], lim = Lim[p];
    float step = (float)exp((double)logstep[p]);
    float zr = lre * step, zi = lim * step;
    double m = exp((double)zr);
    double sv, cv; sincos((double)zi, &sv, &cv);
    float br = (float)(m * cv), bi = (float)(m * sv);
    d_Lbar[p] = make_float2(br, bi);
    // g = (Lbar - 1) / Lam   (complex, fp32 like reference)
    float ar = br - 1.f, ai = bi;
    float den = lre*lre + lim*lim;
    d_g[p] = make_float2((ar*lre + ai*lim)/den, (ai*lre - ar*lim)/den);
    // W = (fp32 Lbar)^CHUNK in double, then powers W^0..W^{NC-1} stored fp32
    double dbr = (double)br, dbi = (double)bi;
    double r  = sqrt(dbr*dbr + dbi*dbi);
    double mm = exp(log(r) * (double)CHUNK);
    double th = atan2(dbi, dbr) * (double)CHUNK;
    double s2, c2; sincos(th, &s2, &c2);
    double Wr = mm*c2, Wi = mm*s2;
    double pr = 1.0, pi_ = 0.0;
    for (int k = 0; k < NC; ++k) {
        d_Wpow[k*PP + p] = make_float2((float)pr, (float)pi_);
        double nr = pr*Wr - pi_*Wi;
        double ni = pr*Wi + pi_*Wr;
        pr = nr; pi_ = ni;
    }
}

// ---------------- K1b: Bg[v][p] = g_p * sum_h embed[v,h]*Bc[p,h] ----------------
__global__ void prep_bg(const float* __restrict__ embed, const float* __restrict__ Bre,
                        const float* __restrict__ Bim) {
    __shared__ float sBr[HH], sBi[HH];
    int p = blockIdx.x;
    for (int h = threadIdx.x; h < HH; h += blockDim.x) {
        sBr[h] = Bre[p*HH + h];
        sBi[h] = Bim[p*HH + h];
    }
    __syncthreads();
    int warp = threadIdx.x >> 5, lane = threadIdx.x & 31;
    float2 g = d_g[p];
    for (int v = warp; v < VV; v += 8) {
        float sr = 0.f, si = 0.f;
        for (int h = lane; h < HH; h += 32) {
            float e = embed[v*HH + h];
            sr = fmaf(e, sBr[h], sr);
            si = fmaf(e, sBi[h], si);
        }
        #pragma unroll
        for (int o = 16; o; o >>= 1) {
            sr += __shfl_xor_sync(0xffffffffu, sr, o);
            si += __shfl_xor_sync(0xffffffffu, si, o);
        }
        if (lane == 0)
            d_Bg[v*PP + p] = make_float2(g.x*sr - g.y*si, g.x*si + g.y*sr);
    }
}

// ---------------- K2: chunked scan, 2 modes/thread, packed f32x2 ----------------
__global__ void __launch_bounds__(192) scan_chunks(const int* __restrict__ tokens) {
    __shared__ int stok[CHUNK];
    int b = blockIdx.y, c = blockIdx.x, t = threadIdx.x;
    for (int i = t; i < CHUNK; i += 192) stok[i] = tokens[b*LL + c*CHUNK + i];
    __syncthreads();
    int p0 = t * 2;
    float2 L0 = d_Lbar[p0], L1 = d_Lbar[p0 + 1];
    u64 Lp0 = pk2(L0.x, L0.x), Lm0 = pk2(-L0.y, L0.y);
    u64 Lp1 = pk2(L1.x, L1.x), Lm1 = pk2(-L1.y, L1.y);
    u64 X0 = 0ull, X1 = 0ull;
    const ulonglong2* __restrict__ bgp = (const ulonglong2*)d_Bg;  // [v*PP/2 + t]
    #pragma unroll 5
    for (int i = 0; i < CHUNK; ++i) {
        ulonglong2 bg = bgp[stok[i]*(PP/2) + t];
        cstep(X0, Lp0, Lm0, bg.x);
        cstep(X1, Lp1, Lm1, bg.y);
    }
    ((ulonglong2*)d_xpart)[(b*NC + c)*(PP/2) + t] = make_ulonglong2(X0, X1);
}

// ---------------- K3: fp32 chunk-combine (independent sum) + 16 emission steps ----------------
__global__ void __launch_bounds__(192) combine_emit(const int* __restrict__ tokens) {
    int b = blockIdx.x;
    int p = blockIdx.y * 192 + threadIdx.x;
    float2 Lb = d_Lbar[p];
    float xr = 0.f, xi = 0.f;
    #pragma unroll
    for (int c = 0; c < NC; ++c) {
        float2 W  = d_Wpow[(NC - 1 - c)*PP + p];
        float2 xp = d_xpart[(b*NC + c)*PP + p];
        xr = fmaf(W.x, xp.x, fmaf(-W.y, xp.y, xr));
        xi = fmaf(W.x, xp.y, fmaf( W.y, xp.x, xi));
    }
    int tk[TOUT];
    #pragma unroll
    for (int j = 0; j < TOUT; ++j) tk[j] = tokens[b*LL + (LL - TOUT) + j];
    #pragma unroll
    for (int j = 0; j < TOUT; ++j) {
        float2 bg = d_Bg[tk[j]*PP + p];
        float nr = fmaf(Lb.x, xr, fmaf(-Lb.y, xi, bg.x));
        float ni = fmaf(Lb.y, xr, fmaf( Lb.x, xi, bg.y));
        xr = nr; xi = ni;
        int r = b*TOUT + j;
        d_Xbig[r*(2*PP) + p]      =  2.f * xr;
        d_Xbig[r*(2*PP) + PP + p] = -2.f * xi;
    }
}

// ---------------- small prep: Cbig = [C_re^T ; C_im^T] ----------------
__global__ void prep_cbig(const float* __restrict__ Cre, const float* __restrict__ Cim) {
    int idx = blockIdx.x*256 + threadIdx.x;      // 2*PP*HH total
    int k = idx / HH, h = idx % HH;
    d_Cbig[idx] = (k < PP) ? Cre[h*PP + k] : Cim[h*PP + (k - PP)];
}

// ---------------- split-K fp32 GEMM (M=N=512) with packed FFMA2 ----------------
__device__ __forceinline__ void gemm_body(const float* __restrict__ A,
                                          const float* __restrict__ B,
                                          float* __restrict__ Cp, int K) {
    __shared__ u64   sA[16][64];    // A values pre-duplicated as (a,a) pairs
    __shared__ float sB[16][64];
    int tid = threadIdx.x;          // 128 threads
    int tn = tid & 7, tm = tid >> 3;     // tn: 8 col-groups(8 cols), tm: 16 row-groups(4 rows)
    int row0 = blockIdx.y * 64, col0 = blockIdx.x * 64;
    int kchunk = K / SPLITK;
    int k0 = blockIdx.z * kchunk;
    u64 acc[4][4] = {};             // [row i][col-pair j]
    int ar = tid >> 1, ak = (tid & 1) * 8;   // A staging: row 0..63, k-half 0/8
    int bk = tid >> 3, bc = (tid & 7) * 8;   // B staging: k-row 0..15, col 0..56
    for (int kk = 0; kk < kchunk; kk += 16) {
        const float* Ap = A + (size_t)(row0 + ar)*K + k0 + kk + ak;
        float4 v0 = *(const float4*)Ap;
        float4 v1 = *(const float4*)(Ap + 4);
        const float* Bp = B + (size_t)(k0 + kk + bk)*HH + col0 + bc;
        float4 w0 = *(const float4*)Bp;
        float4 w1 = *(const float4*)(Bp + 4);
        sA[ak+0][ar] = pk2(v0.x, v0.x); sA[ak+1][ar] = pk2(v0.y, v0.y);
        sA[ak+2][ar] = pk2(v0.z, v0.z); sA[ak+3][ar] = pk2(v0.w, v0.w);
        sA[ak+4][ar] = pk2(v1.x, v1.x); sA[ak+5][ar] = pk2(v1.y, v1.y);
        sA[ak+6][ar] = pk2(v1.z, v1.z); sA[ak+7][ar] = pk2(v1.w, v1.w);
        *(float4*)&sB[bk][bc]     = w0;
        *(float4*)&sB[bk][bc + 4] = w1;
        __syncthreads();
        #pragma unroll
        for (int k = 0; k < 16; ++k) {
            u64 a0 = sA[k][tm*4+0], a1 = sA[k][tm*4+1];
            u64 a2 = sA[k][tm*4+2], a3 = sA[k][tm*4+3];
            ulonglong2 bb0 = ((const ulonglong2*)sB[k])[tn*2];
            ulonglong2 bb1 = ((const ulonglong2*)sB[k])[tn*2 + 1];
            acc[0][0]=fma2(a0,bb0.x,acc[0][0]); acc[0][1]=fma2(a0,bb0.y,acc[0][1]);
            acc[0][2]=fma2(a0,bb1.x,acc[0][2]); acc[0][3]=fma2(a0,bb1.y,acc[0][3]);
            acc[1][0]=fma2(a1,bb0.x,acc[1][0]); acc[1][1]=fma2(a1,bb0.y,acc[1][1]);
            acc[1][2]=fma2(a1,bb1.x,acc[1][2]); acc[1][3]=fma2(a1,bb1.y,acc[1][3]);
            acc[2][0]=fma2(a2,bb0.x,acc[2][0]); acc[2][1]=fma2(a2,bb0.y,acc[2][1]);
            acc[2][2]=fma2(a2,bb1.x,acc[2][2]); acc[2][3]=fma2(a2,bb1.y,acc[2][3]);
            acc[3][0]=fma2(a3,bb0.x,acc[3][0]); acc[3][1]=fma2(a3,bb0.y,acc[3][1]);
            acc[3][2]=fma2(a3,bb1.x,acc[3][2]); acc[3][3]=fma2(a3,bb1.y,acc[3][3]);
        }
        __syncthreads();
    }
    float* Cb = Cp + (size_t)blockIdx.z * (RR*HH);
    #pragma unroll
    for (int i = 0; i < 4; ++i) {
        float* crow = Cb + (size_t)(row0 + tm*4 + i)*HH + col0 + tn*8;
        #pragma unroll
        for (int j = 0; j < 4; ++j) {
            float2 f = upk(acc[i][j]);
            *(float2*)(crow + 2*j) = f;
        }
    }
}

__global__ void __launch_bounds__(128) gemm_xc() {
    gemm_body(d_Xbig, d_Cbig, d_part, 2*PP);
}
__global__ void __launch_bounds__(128) gemm_yw(const float* __restrict__ W1) {
    gemm_body(d_y, W1, d_part, HH);
}

// ---------------- reductions (reduce_y fuses the u*D term) ----------------
__global__ void reduce_y(const int* __restrict__ tokens, const float* __restrict__ embed,
                         const float* __restrict__ D) {
    int i = blockIdx.x*256 + threadIdx.x;
    int r = i / HH, h = i % HH;
    int b = r / TOUT, j = r % TOUT;
    int tok = tokens[b*LL + (LL - TOUT) + j];
    float s = embed[(size_t)tok*HH + h] * D[h];
    #pragma unroll
    for (int z = 0; z < SPLITK; ++z) s += d_part[(size_t)z*RR*HH + i];
    d_y[i] = s;
}
__global__ void reduce_h1(const float* __restrict__ b1) {
    int i = blockIdx.x*256 + threadIdx.x;
    float s = b1[i % HH];
    #pragma unroll
    for (int z = 0; z < SPLITK; ++z) s += d_part[(size_t)z*RR*HH + i];
    d_h1[i] = fmaxf(s, 0.f);
}

// ---------------- final tiny GEMM: out = h1 @ W2 + b2 ----------------
__global__ void final_out(const float* __restrict__ W2, const float* __restrict__ b2,
                          float* __restrict__ out) {
    int idx = blockIdx.x*256 + threadIdx.x;      // RR*VV = 16384
    int r = idx >> 5, v = idx & 31;
    float acc = b2[v];
    const float* hrow = d_h1 + (size_t)r*HH;
    #pragma unroll 8
    for (int h = 0; h < HH; ++h)
        acc = fmaf(hrow[h], W2[h*VV + v], acc);
    out[idx] = acc;
}

// ---------------- launcher ----------------
extern "C" void kernel_launch(void* const* d_in, const int* in_sizes, int n_in,
                              void* d_out, int out_size) {
    const int*   tokens  = (const int*)  d_in[0];
    const float* embed   = (const float*)d_in[1];
    const float* Lre     = (const float*)d_in[2];
    const float* Lim     = (const float*)d_in[3];
    const float* Bre     = (const float*)d_in[4];
    const float* Bim     = (const float*)d_in[5];
    const float* Cre     = (const float*)d_in[6];
    const float* Cim     = (const float*)d_in[7];
    const float* D       = (const float*)d_in[8];
    const float* logstep = (const float*)d_in[9];
    const float* W1      = (const float*)d_in[10];
    const float* b1      = (const float*)d_in[11];
    const float* W2      = (const float*)d_in[12];
    const float* b2      = (const float*)d_in[13];
    float* out = (float*)d_out;

    prep_lbar<<<1, PP>>>(Lre, Lim, logstep);
    prep_bg<<<PP, 256>>>(embed, Bre, Bim);
    scan_chunks<<<dim3(NC, BSZ), 192>>>(tokens);
    combine_emit<<<dim3(BSZ, 2), 192>>>(tokens);
    prep_cbig<<<(2*PP*HH)/256, 256>>>(Cre, Cim);

    gemm_xc<<<dim3(8, 8, SPLITK), 128>>>();
    reduce_y<<<(RR*HH)/256, 256>>>(tokens, embed, D);
    gemm_yw<<<dim3(8, 8, SPLITK), 128>>>(W1);
    reduce_h1<<<(RR*HH)/256, 256>>>(b1);
    final_out<<<(RR*VV)/256, 256>>>(W2, b2, out);
}